// round 1
// baseline (speedup 1.0000x reference)
#include <cuda_runtime.h>

// RoPE: x (4,16,4096,64) fp32, interleaved even/odd pairs.
// out[...,2i]   = cos(a)*x[...,2i] - sin(a)*x[...,2i+1]
// out[...,2i+1] = sin(a)*x[...,2i] + cos(a)*x[...,2i+1]
// a = pos * 10000^(-2i/64), pos = seq index (token_positions is arange, ignored
// by the reference's math, so we ignore it too).

#define SEQ_LEN   4096
#define DK        64
#define TBL_T     (DK / 4)            // 16 float4 entries per position
#define TBL_N     (SEQ_LEN * TBL_T)   // 65536 float4 = 1 MiB

// Scratch: cos/sin table. (c0, s0, c1, s1) for the two pairs covered by one float4 of x.
__device__ float4 g_rope_tbl[TBL_N];

__global__ void __launch_bounds__(256) build_table_kernel() {
    int idx = blockIdx.x * blockDim.x + threadIdx.x;
    if (idx >= TBL_N) return;
    int t   = idx & (TBL_T - 1);     // which float4 within the 64-dim row
    int pos = idx >> 4;              // sequence position

    float fpos = (float)pos;
    int p0 = 2 * t;                  // pair indices covered by this float4
    int p1 = 2 * t + 1;
    // inv_freq = 10000^(-(2p)/64), matching reference fp32 math
    float inv0 = powf(10000.0f, -((float)(2 * p0)) / 64.0f);
    float inv1 = powf(10000.0f, -((float)(2 * p1)) / 64.0f);
    float s0, c0, s1, c1;
    sincosf(fpos * inv0, &s0, &c0);  // accurate sincos (args up to ~4095)
    sincosf(fpos * inv1, &s1, &c1);

    float4 e;
    e.x = c0; e.y = s0; e.z = c1; e.w = s1;
    g_rope_tbl[idx] = e;
}

__global__ void __launch_bounds__(256) rope_kernel(const float4* __restrict__ x,
                                                   float4* __restrict__ out,
                                                   int n4) {
    int idx = blockIdx.x * blockDim.x + threadIdx.x;
    if (idx >= n4) return;

    // Layout: [...(b,h), pos (4096), dim (64)] -> 16 float4 per row.
    int t   = idx & 15;
    int pos = (idx >> 4) & (SEQ_LEN - 1);

    float4 v  = x[idx];
    float4 cs = g_rope_tbl[(pos << 4) | t];   // L2-resident, reused 64x

    float4 o;
    o.x = cs.x * v.x - cs.y * v.y;   // c0*e - s0*o
    o.y = cs.y * v.x + cs.x * v.y;   // s0*e + c0*o
    o.z = cs.z * v.z - cs.w * v.w;
    o.w = cs.w * v.z + cs.z * v.w;
    out[idx] = o;
}

extern "C" void kernel_launch(void* const* d_in, const int* in_sizes, int n_in,
                              void* d_out, int out_size) {
    const float4* x   = (const float4*)d_in[0];
    float4*       out = (float4*)d_out;

    // Build cos/sin table (1 MiB, lands in L2). Deterministic, rebuilt each call.
    build_table_kernel<<<(TBL_N + 255) / 256, 256>>>();

    int n4 = out_size / 4;  // 16,777,216 floats -> 4,194,304 float4
    rope_kernel<<<(n4 + 255) / 256, 256>>>(x, out, n4);
}